// round 3
// baseline (speedup 1.0000x reference)
#include <cuda_runtime.h>
#include <cstdint>

// Decoder: 2-layer LSTM + Luong attention. T=B=S=64, H=E=1024, L=2.
// Software-pipelined: one kernel launch per step carrying staggered segments
// [L1(t-1), OUT(t-4), L0(t), Q(t-2), ATTN(t-3)]. 128-thread blocks, 64x32 tiles.

#define TT 64
#define BB 64
#define SS 64
#define HH 1024

typedef unsigned long long ull;

__device__ __forceinline__ void fma2(ull &d, ull a, ull b) {
    asm volatile("fma.rn.f32x2 %0, %1, %2, %0;" : "+l"(d) : "l"(a), "l"(b));
}
__device__ __forceinline__ ull dup2(float x) {
    ull r;
    asm("mov.b64 %0, {%1, %1};" : "=l"(r) : "r"(__float_as_uint(x)));
    return r;
}
__device__ __forceinline__ float2 unpk(ull v) {
    float2 f;
    f.x = __uint_as_float((unsigned)v);
    f.y = __uint_as_float((unsigned)(v >> 32));
    return f;
}
__device__ __forceinline__ float sigm_(float x) { return 1.f / (1.f + expf(-x)); }

// ---------------- scratch ----------------
__device__ float g_X0[(size_t)TT * BB * 4 * HH];
__device__ float g_h0[2][BB * HH];
__device__ float g_h1[4][BB * HH];
__device__ float g_c0[BB * HH];
__device__ float g_c1[BB * HH];
__device__ float g_q[2][BB * HH];
__device__ float g_wc[2][BB * HH];
__device__ float g_attn[BB * SS];

#define SM_BYTES 17408
// As[2][16][68] floats (8704B) | Ws[2][16][34] ull (8704B)
// epilogue staging reuses region as Cs[32][66] floats (8448B)

// ============================================================
// 64(M) x 32(N) x K GEMM core, 128 threads. C = A @ W^T, W row-major [.,ldW].
// GATE: cols = 4 gates x 8 hidden units (W-row remap).
// PAIR2: A1@W1^T + A2@W2^T (K=2048 total).
// GATHER: A rows gathered via index.
// ============================================================
template <bool PAIR2, bool GATE, bool GATHER>
__device__ __forceinline__ void gemm64x32(
    const float* __restrict__ A1, const float* __restrict__ A2,
    const float* __restrict__ W1, const float* __restrict__ W2,
    int ldW, int nblk, int mbase, const int* __restrict__ gidx,
    char* smraw, ull acc[2][4])
{
    float (*As)[16][68] = (float (*)[16][68])smraw;
    ull   (*Ws)[16][34] = (ull (*)[16][34])(smraw + 8704);

    const int tx  = threadIdx.x;
    const int ar  = tx >> 1, ak = (tx & 1) << 3;   // A fill: row 0..63, k 0/8
    const int wrl = tx >> 2, wk = (tx & 3) << 2;   // W fill: row 0..31, k 0..12
    const int m0  = (tx & 15) << 2;                // compute: 4 rows
    const int n0  = (tx >> 4) << 2;                // compute: 4 cols (0..28)

    const int wr = GATE ? ((wrl >> 3) * HH + nblk * 8 + (wrl & 7))
                        : (nblk * 32 + wrl);
    const float* Ar1 = GATHER ? A1 + (size_t)gidx[mbase + ar] * HH
                              : A1 + (size_t)(mbase + ar) * HH;
    const float* Ar2 = PAIR2 ? A2 + (size_t)ar * HH : nullptr;
    const float* Wr1 = W1 + (size_t)wr * ldW;
    const float* Wr2 = PAIR2 ? W2 + (size_t)wr * ldW : nullptr;

    float4 av0 = *(const float4*)(Ar1 + ak);
    float4 av1 = *(const float4*)(Ar1 + ak + 4);
    float4 wv  = *(const float4*)(Wr1 + wk);

    const int NT = PAIR2 ? 128 : 64;

#define TILE_STEP(BUF, KT)                                                     \
    {                                                                          \
        As[BUF][ak + 0][ar] = av0.x; As[BUF][ak + 1][ar] = av0.y;              \
        As[BUF][ak + 2][ar] = av0.z; As[BUF][ak + 3][ar] = av0.w;              \
        As[BUF][ak + 4][ar] = av1.x; As[BUF][ak + 5][ar] = av1.y;              \
        As[BUF][ak + 6][ar] = av1.z; As[BUF][ak + 7][ar] = av1.w;              \
        Ws[BUF][wk + 0][wrl] = dup2(wv.x); Ws[BUF][wk + 1][wrl] = dup2(wv.y);  \
        Ws[BUF][wk + 2][wrl] = dup2(wv.z); Ws[BUF][wk + 3][wrl] = dup2(wv.w);  \
        __syncthreads();                                                       \
        int kn = (KT) + 1;                                                     \
        if (kn < NT) {                                                         \
            const float *Ap, *Wp; int kk;                                      \
            if (PAIR2 && kn >= 64) { Ap = Ar2; Wp = Wr2; kk = (kn - 64) * 16; }\
            else                   { Ap = Ar1; Wp = Wr1; kk = kn * 16; }       \
            av0 = *(const float4*)(Ap + kk + ak);                              \
            av1 = *(const float4*)(Ap + kk + ak + 4);                          \
            wv  = *(const float4*)(Wp + kk + wk);                              \
        }                                                                      \
        _Pragma("unroll")                                                      \
        for (int k = 0; k < 16; ++k) {                                         \
            ulonglong2 aa  = *(const ulonglong2*)&As[BUF][k][m0];              \
            ulonglong2 w01 = *(const ulonglong2*)&Ws[BUF][k][n0];              \
            ulonglong2 w23 = *(const ulonglong2*)&Ws[BUF][k][n0 + 2];          \
            fma2(acc[0][0], aa.x, w01.x); fma2(acc[1][0], aa.y, w01.x);        \
            fma2(acc[0][1], aa.x, w01.y); fma2(acc[1][1], aa.y, w01.y);        \
            fma2(acc[0][2], aa.x, w23.x); fma2(acc[1][2], aa.y, w23.x);        \
            fma2(acc[0][3], aa.x, w23.y); fma2(acc[1][3], aa.y, w23.y);        \
        }                                                                      \
    }

    for (int kt = 0; kt < NT; kt += 2) {
        TILE_STEP(0, kt)
        TILE_STEP(1, kt + 1)
    }
#undef TILE_STEP
}

// Stage accumulators to smem as Cs[col][row] (pitch 66).
__device__ __forceinline__ void stage_acc(char* smraw, ull acc[2][4]) {
    float* Cs = (float*)smraw;
    const int tx = threadIdx.x;
    const int m0 = (tx & 15) << 2, n0 = (tx >> 4) << 2;
    __syncthreads();  // done reading As/Ws
#pragma unroll
    for (int j = 0; j < 4; ++j) {
        *(float2*)&Cs[(n0 + j) * 66 + m0]     = unpk(acc[0][j]);
        *(float2*)&Cs[(n0 + j) * 66 + m0 + 2] = unpk(acc[1][j]);
    }
    __syncthreads();
}

// Fused LSTM cell epilogue: cols are gate*8 + jj for 8 hidden units.
__device__ __forceinline__ void cell_epi(
    char* smraw, int nblk,
    const float* __restrict__ add,
    const float* __restrict__ B1, const float* __restrict__ B2,
    float* __restrict__ cSt, float* __restrict__ hOut)
{
    float* Cs = (float*)smraw;
    const int tx = threadIdx.x;
#pragma unroll
    for (int it = 0; it < 4; ++it) {
        int idx = tx + it * 128;
        int b = idx & 63, jj = idx >> 6;   // jj 0..7
        int jg = nblk * 8 + jj;
        float gi = Cs[jj * 66 + b];
        float gf = Cs[(8 + jj) * 66 + b];
        float gg = Cs[(16 + jj) * 66 + b];
        float go = Cs[(24 + jj) * 66 + b];
        if (add) {
            const float* ac = add + (size_t)b * 4096 + jg;
            gi += ac[0]; gf += ac[1024]; gg += ac[2048]; go += ac[3072];
        }
        if (B1) {
            gi += B1[jg] + B2[jg];
            gf += B1[1024 + jg] + B2[1024 + jg];
            gg += B1[2048 + jg] + B2[2048 + jg];
            go += B1[3072 + jg] + B2[3072 + jg];
        }
        float ii = sigm_(gi), ff = sigm_(gf);
        float g = tanhf(gg), oo = sigm_(go);
        float c = ff * cSt[b * HH + jg] + ii * g;
        cSt[b * HH + jg] = c;
        hOut[b * HH + jg] = oo * tanhf(c);
    }
}

template <bool BIAS, bool TANH>
__device__ __forceinline__ void store_epi(
    char* smraw, int nbase, int mbase,
    const float* __restrict__ B1, const float* __restrict__ B2,
    float* __restrict__ C, int ldC)
{
    float* Cs = (float*)smraw;
    const int tx = threadIdx.x;
#pragma unroll
    for (int it = 0; it < 16; ++it) {
        int idx = tx + it * 128;
        int row = idx >> 5, col = idx & 31;
        float v = Cs[col * 66 + row];
        int cg = nbase + col;
        if (BIAS) v += B1[cg] + B2[cg];
        if (TANH) v = tanhf(v);
        C[(size_t)(mbase + row) * ldC + cg] = v;
    }
}

// ---------------- step kernel: fused pipeline segments ----------------
struct StepP {
    int nL1, nOut, nL0, nQ, nAt;
    const float *l1A1, *l1A2, *l1W1, *l1W2, *l1B1, *l1B2;
    float *l1C, *l1H;
    const float *oA1, *oA2, *oW;
    float *oOut;
    const float *l0A1, *l0W, *l0Add;
    float *l0C, *l0H;
    const float *qA, *qW;
    float *qOut;
    const float *atQ, *atCtx;
    float *atWc, *atP;
};

__global__ __launch_bounds__(128, 4) void step_k(StepP p) {
    __shared__ __align__(16) char smraw[SM_BYTES];
    const int bid = blockIdx.x;
    const int r0 = p.nL1, r1 = r0 + p.nOut, r2 = r1 + p.nL0, r3 = r2 + p.nQ;
    ull acc[2][4] = {{0, 0, 0, 0}, {0, 0, 0, 0}};

    if (bid < r0) {                       // L1
        int nblk = bid;
        gemm64x32<true, true, false>(p.l1A1, p.l1A2, p.l1W1, p.l1W2, HH,
                                     nblk, 0, nullptr, smraw, acc);
        stage_acc(smraw, acc);
        cell_epi(smraw, nblk, nullptr, p.l1B1, p.l1B2, p.l1C, p.l1H);
    } else if (bid < r1) {                // OUT
        int nblk = bid - r0;
        gemm64x32<true, false, false>(p.oA1, p.oA2, p.oW, p.oW + HH, 2 * HH,
                                      nblk, 0, nullptr, smraw, acc);
        stage_acc(smraw, acc);
        store_epi<false, true>(smraw, nblk * 32, 0, nullptr, nullptr, p.oOut, HH);
    } else if (bid < r2) {                // L0
        int nblk = bid - r1;
        gemm64x32<false, true, false>(p.l0A1, nullptr, p.l0W, nullptr, HH,
                                      nblk, 0, nullptr, smraw, acc);
        stage_acc(smraw, acc);
        cell_epi(smraw, nblk, p.l0Add, nullptr, nullptr, p.l0C, p.l0H);
    } else if (bid < r3) {                // Q
        int nblk = bid - r2;
        gemm64x32<false, false, false>(p.qA, nullptr, p.qW, nullptr, HH,
                                       nblk, 0, nullptr, smraw, acc);
        stage_acc(smraw, acc);
        store_epi<false, false>(smraw, nblk * 32, 0, nullptr, nullptr, p.qOut, HH);
    } else {                              // ATTN (one block per b)
        int b = bid - r3;
        float* qs = (float*)smraw;        // 1024 floats
        float* sc = qs + 1024;            // 64 floats
        const int tx = threadIdx.x;
        *(float4*)&qs[tx * 8]     = *(const float4*)&p.atQ[(size_t)b * HH + tx * 8];
        *(float4*)&qs[tx * 8 + 4] = *(const float4*)&p.atQ[(size_t)b * HH + tx * 8 + 4];
        __syncthreads();
        const int wid = tx >> 5, lane = tx & 31;
        for (int s = wid; s < SS; s += 4) {
            const float* cp = p.atCtx + ((size_t)s * BB + b) * HH;
            float a = 0.f;
#pragma unroll
            for (int i = 0; i < 8; ++i) {
                float4 c4 = *(const float4*)(cp + i * 128 + lane * 4);
                float4 q4 = *(const float4*)&qs[i * 128 + lane * 4];
                a += c4.x * q4.x + c4.y * q4.y + c4.z * q4.z + c4.w * q4.w;
            }
#pragma unroll
            for (int o = 16; o; o >>= 1) a += __shfl_down_sync(0xFFFFFFFFu, a, o);
            if (lane == 0) sc[s] = a;
        }
        __syncthreads();
        if (tx == 0) {
            float mx = sc[0];
            for (int s = 1; s < SS; ++s) mx = fmaxf(mx, sc[s]);
            float sum = 0.f;
            for (int s = 0; s < SS; ++s) { float e = expf(sc[s] - mx); sc[s] = e; sum += e; }
            float inv = 1.f / sum;
            for (int s = 0; s < SS; ++s) sc[s] *= inv;
        }
        __syncthreads();
        if (tx < SS) p.atP[b * SS + tx] = sc[tx];
        for (int k = tx; k < HH; k += 128) {
            float a = 0.f;
#pragma unroll 8
            for (int s = 0; s < SS; ++s)
                a += sc[s] * p.atCtx[((size_t)s * BB + b) * HH + k];
            p.atWc[(size_t)b * HH + k] = a;
        }
    }
}

// ---------------- precompute: X0 = emb[input] @ w_ih0^T + biases ----------------
__global__ __launch_bounds__(128, 4) void pre_k(
    const int* __restrict__ gidx, const float* __restrict__ emb,
    const float* __restrict__ W, const float* __restrict__ B1,
    const float* __restrict__ B2, float* __restrict__ X0)
{
    __shared__ __align__(16) char smraw[SM_BYTES];
    ull acc[2][4] = {{0, 0, 0, 0}, {0, 0, 0, 0}};
    int nblk = blockIdx.x, mbase = blockIdx.y * 64;
    gemm64x32<false, false, true>(emb, nullptr, W, nullptr, HH,
                                  nblk, mbase, gidx, smraw, acc);
    stage_acc(smraw, acc);
    store_epi<true, false>(smraw, nblk * 32, mbase, B1, B2, X0, 4 * HH);
}

__global__ void init_k(const float* __restrict__ h0, const float* __restrict__ c0) {
    int i = blockIdx.x * 256 + threadIdx.x;
    if (i < BB * HH) {
        g_h0[1][i] = h0[i];                 // h0(-1): slot (-1)&1 = 1
        g_h1[3][i] = h0[BB * HH + i];       // h1(-1): slot (-1)&3 = 3
        g_c0[i] = c0[i];
        g_c1[i] = c0[BB * HH + i];
    }
}

__global__ void final_k(float* __restrict__ hf, float* __restrict__ cf,
                        float* __restrict__ at) {
    int i = blockIdx.x * 256 + threadIdx.x;
    if (i < BB * HH) {
        hf[i] = g_h0[1][i];                 // h0(63): 63&1 = 1
        hf[BB * HH + i] = g_h1[3][i];       // h1(63): 63&3 = 3
        cf[i] = g_c0[i];
        cf[BB * HH + i] = g_c1[i];
    }
    if (i < BB * SS) at[i] = g_attn[i];
}

extern "C" void kernel_launch(void* const* d_in, const int* in_sizes, int n_in,
                              void* d_out, int out_size) {
    (void)in_sizes; (void)n_in; (void)out_size;
    const int*   inp   = (const int*)d_in[0];
    const float* h0    = (const float*)d_in[1];
    const float* c0    = (const float*)d_in[2];
    const float* ctx   = (const float*)d_in[3];
    const float* emb   = (const float*)d_in[4];
    const float* w_ih  = (const float*)d_in[5];
    const float* w_hh  = (const float*)d_in[6];
    const float* b_ih  = (const float*)d_in[7];
    const float* b_hh  = (const float*)d_in[8];
    const float* w_in  = (const float*)d_in[9];
    const float* w_out = (const float*)d_in[10];

    float* out  = (float*)d_out;
    float* outs = out;
    float* hf   = out + (size_t)TT * BB * HH;
    float* cf   = hf + 2 * BB * HH;
    float* at   = cf + 2 * BB * HH;

    float *X0, *H0, *H1, *C0, *C1, *Q, *WC, *AT;
    cudaGetSymbolAddress((void**)&X0, g_X0);
    cudaGetSymbolAddress((void**)&H0, g_h0);
    cudaGetSymbolAddress((void**)&H1, g_h1);
    cudaGetSymbolAddress((void**)&C0, g_c0);
    cudaGetSymbolAddress((void**)&C1, g_c1);
    cudaGetSymbolAddress((void**)&Q,  g_q);
    cudaGetSymbolAddress((void**)&WC, g_wc);
    cudaGetSymbolAddress((void**)&AT, g_attn);
    const int BH = BB * HH;

    init_k<<<256, 256>>>(h0, c0);
    pre_k<<<dim3(128, 64), 128>>>(inp, emb, w_ih, b_ih, b_hh, X0);

    // Pipeline: launch k carries L1(k-1), OUT(k-4), L0(k), Q(k-2), ATTN(k-3).
    for (int k = 0; k <= 67; ++k) {
        StepP p = {};
        int tL1 = k - 1, tL0 = k, tQ = k - 2, tAt = k - 3, tOut = k - 4;
        if (tL1 >= 0 && tL1 < TT) {
            p.nL1 = 128;
            p.l1A1 = H0 + (tL1 & 1) * BH;
            p.l1A2 = H1 + ((tL1 - 1) & 3) * BH;
            p.l1W1 = w_ih + (size_t)4 * HH * HH;
            p.l1W2 = w_hh + (size_t)4 * HH * HH;
            p.l1B1 = b_ih + 4 * HH;
            p.l1B2 = b_hh + 4 * HH;
            p.l1C = C1;
            p.l1H = H1 + (tL1 & 3) * BH;
        }
        if (tOut >= 0 && tOut < TT) {
            p.nOut = 32;
            p.oA1 = WC + (tOut & 1) * BH;
            p.oA2 = H1 + (tOut & 3) * BH;
            p.oW = w_out;
            p.oOut = outs + (size_t)tOut * BH;
        }
        if (tL0 >= 0 && tL0 < TT) {
            p.nL0 = 128;
            p.l0A1 = H0 + ((tL0 + 1) & 1) * BH;
            p.l0W = w_hh;
            p.l0Add = X0 + (size_t)tL0 * BB * 4 * HH;
            p.l0C = C0;
            p.l0H = H0 + (tL0 & 1) * BH;
        }
        if (tQ >= 0 && tQ < TT) {
            p.nQ = 32;
            p.qA = H1 + (tQ & 3) * BH;
            p.qW = w_in;
            p.qOut = Q + (tQ & 1) * BH;
        }
        if (tAt >= 0 && tAt < TT) {
            p.nAt = 64;
            p.atQ = Q + (tAt & 1) * BH;
            p.atCtx = ctx;
            p.atWc = WC + (tAt & 1) * BH;
            p.atP = AT;
        }
        int grid = p.nL1 + p.nOut + p.nL0 + p.nQ + p.nAt;
        if (grid > 0) step_k<<<grid, 128>>>(p);
    }

    final_k<<<512, 256>>>(hf, cf, at);
}

// round 5
// speedup vs baseline: 2.8014x; 2.8014x over previous
#include <cuda_runtime.h>
#include <cuda_bf16.h>
#include <cstdint>

// Decoder: 2-layer LSTM + Luong attention. T=B=S=64, H=E=1024, L=2.
// Warp-level mma.sync bf16 (3-way split precision), pipelined step launches.

#define TT 64
#define BB 64
#define SS 64
#define HH 1024
#define BH (BB * HH)

typedef unsigned long long ull;
typedef __nv_bfloat16 bf16;

__device__ __forceinline__ float sigm_(float x) { return 1.f / (1.f + expf(-x)); }
__device__ __forceinline__ void split2(float v, bf16& hi, bf16& lo) {
    hi = __float2bfloat16(v);
    lo = __float2bfloat16(v - __bfloat162float(hi));
}

// ------------------------------- scratch -------------------------------
__device__ __align__(256) bf16 g_Wih_h[8388608], g_Wih_l[8388608];
__device__ __align__(256) bf16 g_Whh_h[8388608], g_Whh_l[8388608];
__device__ __align__(256) bf16 g_Win_h[1048576], g_Win_l[1048576];
__device__ __align__(256) bf16 g_Wo_h[2097152],  g_Wo_l[2097152];
__device__ __align__(256) bf16 g_XEh[4194304],   g_XEl[4194304];
__device__ float g_X0[(size_t)4096 * 4096];        // [t*64+b][4096 gate cols]
__device__ float g_h0F[2][BH], g_h1F[4][BH], g_c0F[BH], g_c1F[BH];
__device__ __align__(256) bf16 g_h0H[2][BH], g_h0L[2][BH];
__device__ __align__(256) bf16 g_h1H[4][BH], g_h1L[4][BH];
__device__ __align__(256) bf16 g_wcH[2][BH], g_wcL[2][BH];
__device__ float g_qF[2][BH];
__device__ float g_attn[BB * SS];

// ----------------------------- ptx helpers -----------------------------
__device__ __forceinline__ uint32_t s2u(const void* p) {
    uint32_t a;
    asm("{ .reg .u64 t; cvta.to.shared.u64 t, %1; cvt.u32.u64 %0, t; }"
        : "=r"(a) : "l"(p));
    return a;
}
__device__ __forceinline__ void cpa16(uint32_t dst, const void* src) {
    asm volatile("cp.async.cg.shared.global [%0], [%1], 16;"
                 :: "r"(dst), "l"(src) : "memory");
}
__device__ __forceinline__ void ldsm4(uint32_t* r, uint32_t addr) {
    asm volatile("ldmatrix.sync.aligned.m8n8.x4.shared.b16 {%0,%1,%2,%3}, [%4];"
                 : "=r"(r[0]), "=r"(r[1]), "=r"(r[2]), "=r"(r[3]) : "r"(addr));
}
__device__ __forceinline__ void mma16816(float* d, const uint32_t* a, const uint32_t* b) {
    asm volatile(
        "mma.sync.aligned.m16n8k16.row.col.f32.bf16.bf16.f32 "
        "{%0,%1,%2,%3},{%4,%5,%6,%7},{%8,%9},{%0,%1,%2,%3};"
        : "+f"(d[0]), "+f"(d[1]), "+f"(d[2]), "+f"(d[3])
        : "r"(a[0]), "r"(a[1]), "r"(a[2]), "r"(a[3]), "r"(b[0]), "r"(b[1]));
}

// ---------------------------- GEMM segment -----------------------------
// C[64 m(batch), 64 n] = A @ W^T.  A rows [m][1024] bf16 hi/lo; W rows [n][wld].
// GATE: n cols = 4 gates x 16 hidden units (W-row remap for fused LSTM).
// PAIR2: K=2048, second half from A2/W2. EPI 0 = LSTM cell, 1 = store.
struct Seg {
    const bf16 *A1h, *A1l, *A2h, *A2l;
    const bf16 *W1h, *W1l, *W2h, *W2l;
    int wld, K;
    const float *addC, *bias1, *bias2;
    float *cSt, *hF;
    bf16 *hH, *hL;
    float *outC; int ldC, doTanh;
};

// smem: 2 bufs x (Ah 5120 | Al 5120 | Wh 5120 | Wl 5120) = 40960 bytes.
// Rows padded to 80B (k32 = 64B data + 16B pad) -> conflict-free ldmatrix.
#define SMB 40960

template <bool GATE, bool PAIR2, int EPI>
__device__ void mgemm(const Seg& a, char* sm, int mblk, int nblk) {
    const int tx = threadIdx.x;
    const int wid = tx >> 5, lane = tx & 31;
    const int wm = (wid & 3) << 4;       // warp m offset (0..48)
    const int wn = (wid >> 2) << 5;      // warp n offset (0 or 32)
    const uint32_t smb = s2u(sm);

    // staging mapping: thread -> (row, 16B unit)
    const int sr = tx >> 2, su = tx & 3;
    const int wr = GATE ? ((sr >> 4) * HH + nblk * 16 + (sr & 15))
                        : (nblk * 64 + sr);
    const int am = mblk * 64 + sr;

    float acc[4][4] = {};
    const int nc = a.K >> 5;

    // ldmatrix per-lane offsets (within one buffer)
    const uint32_t aoff = (uint32_t)((wm + (lane & 15)) * 80 + ((lane >> 4) << 4));
    const uint32_t boff = (uint32_t)((wn + ((lane >> 4) << 3) + (lane & 7)) * 80
                                     + (((lane >> 3) & 1) << 4));

#define STAGE(c)                                                               \
    {                                                                          \
        int kg = (c) << 5;                                                     \
        const bf16 *a1, *a2, *w1, *w2; int kl;                                 \
        if (PAIR2 && kg >= 1024) {                                             \
            a1 = a.A2h; a2 = a.A2l; w1 = a.W2h; w2 = a.W2l; kl = kg - 1024;    \
        } else {                                                               \
            a1 = a.A1h; a2 = a.A1l; w1 = a.W1h; w2 = a.W1l; kl = kg;           \
        }                                                                      \
        uint32_t db = smb + ((c) & 1) * 20480 + sr * 80 + (su << 4);           \
        size_t ao = (size_t)am * 1024 + kl + su * 8;                           \
        size_t wo = (size_t)wr * a.wld + kl + su * 8;                          \
        cpa16(db,         a1 + ao);                                            \
        cpa16(db + 5120,  a2 + ao);                                            \
        cpa16(db + 10240, w1 + wo);                                            \
        cpa16(db + 15360, w2 + wo);                                            \
        asm volatile("cp.async.commit_group;" ::: "memory");                   \
    }

    STAGE(0)
    for (int c = 0; c < nc; ++c) {
        if (c + 1 < nc) {
            STAGE(c + 1)
            asm volatile("cp.async.wait_group 1;" ::: "memory");
        } else {
            asm volatile("cp.async.wait_group 0;" ::: "memory");
        }
        __syncthreads();
        const uint32_t base = smb + (c & 1) * 20480;
#pragma unroll
        for (int kk = 0; kk < 2; ++kk) {
            uint32_t ah[4], al[4], bh[8], bl[8];
            ldsm4(ah, base + aoff + kk * 32);
            ldsm4(al, base + 5120 + aoff + kk * 32);
            ldsm4(bh,     base + 10240 + boff + kk * 32);
            ldsm4(bh + 4, base + 10240 + boff + 16 * 80 + kk * 32);
            ldsm4(bl,     base + 15360 + boff + kk * 32);
            ldsm4(bl + 4, base + 15360 + boff + 16 * 80 + kk * 32);
#pragma unroll
            for (int nt = 0; nt < 4; ++nt) {
                mma16816(acc[nt], ah, bh + 2 * nt);
                mma16816(acc[nt], ah, bl + 2 * nt);
                mma16816(acc[nt], al, bh + 2 * nt);
            }
        }
        __syncthreads();
    }
#undef STAGE

    // stage C to smem as St[col][row], pitch 66 (conflict-free)
    float* St = (float*)sm;
    const int rr = wm + (lane >> 2);
#pragma unroll
    for (int nt = 0; nt < 4; ++nt) {
        int cc = wn + nt * 8 + ((lane & 3) << 1);
        St[cc * 66 + rr]           = acc[nt][0];
        St[(cc + 1) * 66 + rr]     = acc[nt][1];
        St[cc * 66 + rr + 8]       = acc[nt][2];
        St[(cc + 1) * 66 + rr + 8] = acc[nt][3];
    }
    __syncthreads();

    if (EPI == 0) {      // fused LSTM cell: cols = gate*16 + jj
#pragma unroll
        for (int it = 0; it < 4; ++it) {
            int idx = tx + it * 256;
            int b = idx & 63, jj = idx >> 6;          // jj 0..15
            int jg = nblk * 16 + jj;
            float gi = St[jj * 66 + b];
            float gf = St[(16 + jj) * 66 + b];
            float gg = St[(32 + jj) * 66 + b];
            float go = St[(48 + jj) * 66 + b];
            if (a.addC) {
                const float* ac = a.addC + (size_t)b * 4096 + jg;
                gi += ac[0]; gf += ac[1024]; gg += ac[2048]; go += ac[3072];
            }
            if (a.bias1) {
                gi += a.bias1[jg] + a.bias2[jg];
                gf += a.bias1[1024 + jg] + a.bias2[1024 + jg];
                gg += a.bias1[2048 + jg] + a.bias2[2048 + jg];
                go += a.bias1[3072 + jg] + a.bias2[3072 + jg];
            }
            float cc2 = sigm_(gf) * a.cSt[b * HH + jg] + sigm_(gi) * tanhf(gg);
            a.cSt[b * HH + jg] = cc2;
            float h = sigm_(go) * tanhf(cc2);
            a.hF[b * HH + jg] = h;
            split2(h, a.hH[b * HH + jg], a.hL[b * HH + jg]);
        }
    } else {             // plain store (optional bias / tanh)
#pragma unroll
        for (int it = 0; it < 16; ++it) {
            int idx = tx + it * 256;
            int row = idx >> 6, col = idx & 63;
            float v = St[col * 66 + row];
            int cg = nblk * 64 + col;
            if (a.bias1) v += a.bias1[cg] + a.bias2[cg];
            if (a.doTanh) v = tanhf(v);
            a.outC[(size_t)(mblk * 64 + row) * a.ldC + cg] = v;
        }
    }
}

// ------------------------------ step kernel ----------------------------
struct StepP {
    int nL1, nOut, nL0, nQ, nAt;
    Seg l1, o, l0, q;
    const float *atQ, *atCtx;
    bf16 *atWcH, *atWcL;
    float* atP;
};

__global__ __launch_bounds__(256) void step_k(StepP p) {
    __shared__ __align__(16) char sm[SMB];
    const int bid = blockIdx.x;
    const int r0 = p.nL1, r1 = r0 + p.nOut, r2 = r1 + p.nL0, r3 = r2 + p.nQ;

    if (bid < r0) {
        mgemm<true, true, 0>(p.l1, sm, 0, bid);
    } else if (bid < r1) {
        mgemm<false, true, 1>(p.o, sm, 0, bid - r0);
    } else if (bid < r2) {
        mgemm<true, false, 0>(p.l0, sm, 0, bid - r1);
    } else if (bid < r3) {
        mgemm<false, false, 1>(p.q, sm, 0, bid - r2);
    } else {                              // ATTN: one block per batch b
        int b = bid - r3;
        float* qs = (float*)sm;           // 1024 floats
        float* sc = qs + 1024;            // 64 floats
        const int tx = threadIdx.x;
        *(float4*)&qs[tx * 4] = *(const float4*)&p.atQ[(size_t)b * HH + tx * 4];
        __syncthreads();
        const int wid = tx >> 5, lane = tx & 31;
        for (int s = wid; s < SS; s += 8) {
            const float* cp = p.atCtx + ((size_t)s * BB + b) * HH;
            float acc = 0.f;
#pragma unroll
            for (int i = 0; i < 8; ++i) {
                float4 c4 = *(const float4*)(cp + i * 128 + lane * 4);
                float4 q4 = *(const float4*)&qs[i * 128 + lane * 4];
                acc += c4.x * q4.x + c4.y * q4.y + c4.z * q4.z + c4.w * q4.w;
            }
#pragma unroll
            for (int o = 16; o; o >>= 1) acc += __shfl_down_sync(0xFFFFFFFFu, acc, o);
            if (lane == 0) sc[s] = acc;
        }
        __syncthreads();
        if (tx == 0) {
            float mx = sc[0];
            for (int s = 1; s < SS; ++s) mx = fmaxf(mx, sc[s]);
            float sum = 0.f;
            for (int s = 0; s < SS; ++s) { float e = expf(sc[s] - mx); sc[s] = e; sum += e; }
            float inv = 1.f / sum;
            for (int s = 0; s < SS; ++s) sc[s] *= inv;
        }
        __syncthreads();
        if (tx < SS) p.atP[b * SS + tx] = sc[tx];
        for (int k = tx; k < HH; k += 256) {
            float acc = 0.f;
#pragma unroll 8
            for (int s = 0; s < SS; ++s)
                acc += sc[s] * p.atCtx[((size_t)s * BB + b) * HH + k];
            split2(acc, p.atWcH[(size_t)b * HH + k], p.atWcL[(size_t)b * HH + k]);
        }
    }
}

// ---------------- X0 precompute: emb[input] @ w_ih0^T + biases ----------
__global__ __launch_bounds__(256) void x0_k(StepP p) {
    __shared__ __align__(16) char sm[SMB];
    mgemm<false, false, 1>(p.l0, sm, blockIdx.y, blockIdx.x);
}

// ----------------------------- init kernels ----------------------------
__global__ void split_w(const float* __restrict__ w_ih, const float* __restrict__ w_hh,
                        const float* __restrict__ w_in, const float* __restrict__ w_out) {
    const size_t N = 19922944;
    for (size_t i = (size_t)blockIdx.x * 256 + threadIdx.x; i < N;
         i += (size_t)gridDim.x * 256) {
        float v; bf16 *dh, *dl; size_t j;
        if (i < 8388608) {
            j = i; v = w_ih[j]; dh = g_Wih_h; dl = g_Wih_l;
        } else if (i < 16777216) {
            j = i - 8388608; v = w_hh[j]; dh = g_Whh_h; dl = g_Whh_l;
        } else if (i < 17825792) {
            j = i - 16777216; v = w_in[j]; dh = g_Win_h; dl = g_Win_l;
        } else {
            j = i - 17825792; v = w_out[j]; dh = g_Wo_h; dl = g_Wo_l;
        }
        split2(v, dh[j], dl[j]);
    }
}

__global__ void gather_xe(const int* __restrict__ inp, const float* __restrict__ emb) {
    size_t i = (size_t)blockIdx.x * 256 + threadIdx.x;
    if (i < 4194304) {
        size_t tb = i >> 10, k = i & 1023;
        float v = emb[(size_t)inp[tb] * 1024 + k];
        split2(v, g_XEh[i], g_XEl[i]);
    }
}

__global__ void init_sk(const float* __restrict__ h0, const float* __restrict__ c0) {
    int i = blockIdx.x * 256 + threadIdx.x;
    if (i < BH) {
        float a = h0[i], b = h0[BH + i];
        g_h0F[1][i] = a; split2(a, g_h0H[1][i], g_h0L[1][i]);   // h0(-1): slot 1
        g_h1F[3][i] = b; split2(b, g_h1H[3][i], g_h1L[3][i]);   // h1(-1): slot 3
        g_c0F[i] = c0[i];
        g_c1F[i] = c0[BH + i];
    }
}

__global__ void final_k(float* __restrict__ hf, float* __restrict__ cf,
                        float* __restrict__ at) {
    int i = blockIdx.x * 256 + threadIdx.x;
    if (i < BH) {
        hf[i] = g_h0F[1][i];            // h0(63): 63&1 = 1
        hf[BH + i] = g_h1F[3][i];       // h1(63): 63&3 = 3
        cf[i] = g_c0F[i];
        cf[BH + i] = g_c1F[i];
    }
    if (i < BB * SS) at[i] = g_attn[i];
}

// ------------------------------- launch --------------------------------
extern "C" void kernel_launch(void* const* d_in, const int* in_sizes, int n_in,
                              void* d_out, int out_size) {
    (void)in_sizes; (void)n_in; (void)out_size;
    const int*   inp   = (const int*)d_in[0];
    const float* h0    = (const float*)d_in[1];
    const float* c0    = (const float*)d_in[2];
    const float* ctx   = (const float*)d_in[3];
    const float* emb   = (const float*)d_in[4];
    const float* w_ih  = (const float*)d_in[5];
    const float* w_hh  = (const float*)d_in[6];
    const float* b_ih  = (const float*)d_in[7];
    const float* b_hh  = (const float*)d_in[8];
    const float* w_in  = (const float*)d_in[9];
    const float* w_out = (const float*)d_in[10];

    float* out  = (float*)d_out;
    float* outs = out;
    float* hf   = out + (size_t)TT * BH;
    float* cf   = hf + 2 * BH;
    float* at   = cf + 2 * BH;

    bf16 *WihH, *WihL, *WhhH, *WhhL, *WinH, *WinL, *WoH, *WoL, *XEh, *XEl;
    bf16 *h0H, *h0L, *h1H, *h1L, *wcH, *wcL;
    float *h0F, *h1F, *c0F, *c1F, *qF, *X0, *AT;
    cudaGetSymbolAddress((void**)&WihH, g_Wih_h); cudaGetSymbolAddress((void**)&WihL, g_Wih_l);
    cudaGetSymbolAddress((void**)&WhhH, g_Whh_h); cudaGetSymbolAddress((void**)&WhhL, g_Whh_l);
    cudaGetSymbolAddress((void**)&WinH, g_Win_h); cudaGetSymbolAddress((void**)&WinL, g_Win_l);
    cudaGetSymbolAddress((void**)&WoH,  g_Wo_h);  cudaGetSymbolAddress((void**)&WoL,  g_Wo_l);
    cudaGetSymbolAddress((void**)&XEh,  g_XEh);   cudaGetSymbolAddress((void**)&XEl,  g_XEl);
    cudaGetSymbolAddress((void**)&h0F, g_h0F); cudaGetSymbolAddress((void**)&h1F, g_h1F);
    cudaGetSymbolAddress((void**)&h0H, g_h0H); cudaGetSymbolAddress((void**)&h0L, g_h0L);
    cudaGetSymbolAddress((void**)&h1H, g_h1H); cudaGetSymbolAddress((void**)&h1L, g_h1L);
    cudaGetSymbolAddress((void**)&c0F, g_c0F); cudaGetSymbolAddress((void**)&c1F, g_c1F);
    cudaGetSymbolAddress((void**)&qF,  g_qF);
    cudaGetSymbolAddress((void**)&wcH, g_wcH); cudaGetSymbolAddress((void**)&wcL, g_wcL);
    cudaGetSymbolAddress((void**)&X0,  g_X0);
    cudaGetSymbolAddress((void**)&AT,  g_attn);

    split_w<<<16384, 256>>>(w_ih, w_hh, w_in, w_out);
    gather_xe<<<16384, 256>>>(inp, emb);
    init_sk<<<256, 256>>>(h0, c0);

    {   // X0 = XE @ w_ih0^T + b_ih0 + b_hh0, grid (64 nblk, 64 mblk)
        StepP p = {};
        Seg& s = p.l0;
        s.A1h = XEh; s.A1l = XEl;
        s.W1h = WihH; s.W1l = WihL; s.wld = 1024; s.K = 1024;
        s.bias1 = b_ih; s.bias2 = b_hh;
        s.outC = X0; s.ldC = 4096; s.doTanh = 0;
        x0_k<<<dim3(64, 64), 256>>>(p);
    }

    // Pipeline: launch k carries L1(k-1), OUT(k-4), L0(k), Q(k-2), ATTN(k-3).
    for (int k = 0; k <= 67; ++k) {
        StepP p = {};
        int tL1 = k - 1, tL0 = k, tQ = k - 2, tAt = k - 3, tOut = k - 4;
        if (tL1 >= 0 && tL1 < TT) {
            p.nL1 = 64;
            Seg& s = p.l1;
            s.A1h = h0H + (size_t)(tL1 & 1) * BH; s.A1l = h0L + (size_t)(tL1 & 1) * BH;
            s.A2h = h1H + (size_t)((tL1 - 1) & 3) * BH;
            s.A2l = h1L + (size_t)((tL1 - 1) & 3) * BH;
            s.W1h = WihH + 4194304; s.W1l = WihL + 4194304;
            s.W2h = WhhH + 4194304; s.W2l = WhhL + 4194304;
            s.wld = 1024; s.K = 2048;
            s.bias1 = b_ih + 4096; s.bias2 = b_hh + 4096;
            s.cSt = c1F;
            s.hF = h1F + (size_t)(tL1 & 3) * BH;
            s.hH = h1H + (size_t)(tL1 & 3) * BH;
            s.hL = h1L + (size_t)(tL1 & 3) * BH;
        }
        if (tOut >= 0 && tOut < TT) {
            p.nOut = 16;
            Seg& s = p.o;
            s.A1h = wcH + (size_t)(tOut & 1) * BH; s.A1l = wcL + (size_t)(tOut & 1) * BH;
            s.A2h = h1H + (size_t)(tOut & 3) * BH; s.A2l = h1L + (size_t)(tOut & 3) * BH;
            s.W1h = WoH; s.W1l = WoL;
            s.W2h = WoH + 1024; s.W2l = WoL + 1024;
            s.wld = 2048; s.K = 2048;
            s.outC = outs + (size_t)tOut * BH; s.ldC = HH; s.doTanh = 1;
        }
        if (tL0 >= 0 && tL0 < TT) {
            p.nL0 = 64;
            Seg& s = p.l0;
            s.A1h = h0H + (size_t)((tL0 + 1) & 1) * BH;
            s.A1l = h0L + (size_t)((tL0 + 1) & 1) * BH;
            s.W1h = WhhH; s.W1l = WhhL; s.wld = 1024; s.K = 1024;
            s.addC = X0 + (size_t)tL0 * 64 * 4096;
            s.cSt = c0F;
            s.hF = h0F + (size_t)(tL0 & 1) * BH;
            s.hH = h0H + (size_t)(tL0 & 1) * BH;
            s.hL = h0L + (size_t)(tL0 & 1) * BH;
        }
        if (tQ >= 0 && tQ < TT) {
            p.nQ = 16;
            Seg& s = p.q;
            s.A1h = h1H + (size_t)(tQ & 3) * BH; s.A1l = h1L + (size_t)(tQ & 3) * BH;
            s.W1h = WinH; s.W1l = WinL; s.wld = 1024; s.K = 1024;
            s.outC = qF + (size_t)(tQ & 1) * BH; s.ldC = HH; s.doTanh = 0;
        }
        if (tAt >= 0 && tAt < TT) {
            p.nAt = 64;
            p.atQ = qF + (size_t)(tAt & 1) * BH;
            p.atCtx = ctx;
            p.atWcH = wcH + (size_t)(tAt & 1) * BH;
            p.atWcL = wcL + (size_t)(tAt & 1) * BH;
            p.atP = AT;
        }
        int grid = p.nL1 + p.nOut + p.nL0 + p.nQ + p.nAt;
        if (grid > 0) step_k<<<grid, 256>>>(p);
    }

    final_k<<<512, 256>>>(hf, cf, at);
}